// round 17
// baseline (speedup 1.0000x reference)
#include <cuda_runtime.h>
#include <cuda_bf16.h>
#include <cuda_fp16.h>
#include <math.h>
#include <stdint.h>

// Problem constants (fixed by setup_inputs)
#define BB   4
#define C2   512        // deep channels
#define DD   32         // d = 2*C/16
#define HWD  4096       // 64*64 deep spatial
#define OC   256        // out channels of K conv
#define CIN  256        // shallow channels
#define PIX  16384      // 128*128 shallow spatial

typedef unsigned long long ull;

// Scratch (device globals: allocation-free)
__device__ float g_maxout[BB * DD * HWD];
__device__ float g_mpart[4][BB * DD * HWD];                            // split-K partials
__device__ float g_qmax [BB * HWD];
__device__ float g_qmean[BB * HWD];
__device__ float g_scale[BB * HWD];
__device__ float g_litpart[BB * DD * 4];
__device__ float g_Kx[(size_t)BB * OC * PIX];                          // 64MB
__device__ __align__(16) __half g_Wh[OC * CIN];                        // fp16 weights
__device__ __align__(16) __half g_Xh[(size_t)BB * CIN * PIX];          // fp16 shallow, [b][c][p]

// ---------------------------------------------------------------------------
// PTX helpers
// ---------------------------------------------------------------------------
__device__ __forceinline__ uint32_t smem_u32(const void* p) {
    uint32_t a;
    asm("{ .reg .u64 t; cvta.to.shared.u64 t, %1; cvt.u32.u64 %0, t; }"
        : "=r"(a) : "l"(p));
    return a;
}
__device__ __forceinline__ void cp16(uint32_t dst, const void* src) {
    asm volatile("cp.async.cg.shared.global [%0], [%1], 16;"
                 :: "r"(dst), "l"(src) : "memory");
}
__device__ __forceinline__ void ldsm4(uint32_t* r, uint32_t addr) {
    asm volatile("ldmatrix.sync.aligned.m8n8.x4.shared.b16 {%0,%1,%2,%3}, [%4];"
                 : "=r"(r[0]), "=r"(r[1]), "=r"(r[2]), "=r"(r[3]) : "r"(addr));
}
__device__ __forceinline__ void ldsm4t(uint32_t* r, uint32_t addr) {
    asm volatile("ldmatrix.sync.aligned.m8n8.x4.trans.shared.b16 {%0,%1,%2,%3}, [%4];"
                 : "=r"(r[0]), "=r"(r[1]), "=r"(r[2]), "=r"(r[3]) : "r"(addr));
}
__device__ __forceinline__ void mma_f16(float* c, const uint32_t* a, const uint32_t* b) {
    asm volatile(
        "mma.sync.aligned.m16n8k16.row.col.f32.f16.f16.f32 "
        "{%0,%1,%2,%3}, {%4,%5,%6,%7}, {%8,%9}, {%0,%1,%2,%3};"
        : "+f"(c[0]), "+f"(c[1]), "+f"(c[2]), "+f"(c[3])
        : "r"(a[0]), "r"(a[1]), "r"(a[2]), "r"(a[3]), "r"(b[0]), "r"(b[1]));
}
__device__ __forceinline__ void ffma2(ull& d, ull a, ull b) {
    asm("fma.rn.f32x2 %0, %1, %2, %0;" : "+l"(d) : "l"(a), "l"(b));
}
__device__ __forceinline__ ull packf2(float lo, float hi) {
    ull v; asm("mov.b64 %0, {%1, %2};" : "=l"(v) : "f"(lo), "f"(hi)); return v;
}
__device__ __forceinline__ void unpackf2(float& lo, float& hi, ull v) {
    asm("mov.b64 {%0, %1}, %2;" : "=f"(lo), "=f"(hi) : "l"(v));
}

// ---------------------------------------------------------------------------
// Kernel 1a: partial max_out over a 128-channel chunk (split-K x4), FFMA2.
// ---------------------------------------------------------------------------
__global__ void __launch_bounds__(128)
k_maxout_part(const float* __restrict__ deep, const float* __restrict__ ksa_w)
{
    __shared__ ull ws2[32 * 128];   // 32KB, dup-packed (w,w)
    int b = blockIdx.y, chunk = blockIdx.z;
    int tid = threadIdx.x;
    int dh = tid & 1;               // d half
    int pq = tid >> 1;              // pixel quad 0..63
    int px = blockIdx.x * 256 + pq * 4;

    for (int i = tid; i < 32 * 128; i += 128) {
        int d = i >> 7, c = i & 127;
        float w = ksa_w[d * C2 + chunk * 128 + c];
        ws2[i] = packf2(w, w);
    }
    __syncthreads();

    ull acc0[16], acc1[16];
#pragma unroll
    for (int d = 0; d < 16; d++) { acc0[d] = 0ull; acc1[d] = 0ull; }

    const float* dp = deep + ((size_t)b * C2 + chunk * 128) * HWD + px;
    const ull* wrow = ws2 + (dh * 16) * 128;
#pragma unroll 2
    for (int c = 0; c < 128; c++) {
        float4 x = *reinterpret_cast<const float4*>(dp + (size_t)c * HWD);
        ull xp0 = packf2(x.x, x.y);
        ull xp1 = packf2(x.z, x.w);
#pragma unroll
        for (int d = 0; d < 16; d++) {
            ull w = wrow[d * 128 + c];
            ffma2(acc0[d], w, xp0);
            ffma2(acc1[d], w, xp1);
        }
    }

    float* op = g_mpart[chunk] + ((size_t)b * DD + dh * 16) * HWD + px;
#pragma unroll
    for (int d = 0; d < 16; d++) {
        float a, bb_, c, dd_;
        unpackf2(a, bb_, acc0[d]);
        unpackf2(c, dd_, acc1[d]);
        *reinterpret_cast<float2*>(op + (size_t)d * HWD)     = make_float2(a, bb_);
        *reinterpret_cast<float2*>(op + (size_t)d * HWD + 2) = make_float2(c, dd_);
    }
}

// ---------------------------------------------------------------------------
// Kernel 1b: combine partials -> maxout, qmax, qmean (parallel).
// ---------------------------------------------------------------------------
__global__ void __launch_bounds__(512)
k_maxcomb(const float* __restrict__ ksa_b)
{
    __shared__ float smx[8][64];
    __shared__ float ssm[8][64];
    int tid = threadIdx.x;
    int pl = tid & 63;
    int dg = tid >> 6;
    int gp = blockIdx.x * 64 + pl;
    int b = gp >> 12;
    int p = gp & (HWD - 1);

    float mx = -1e30f, sm = 0.f;
#pragma unroll
    for (int k = 0; k < 4; k++) {
        int d = dg * 4 + k;
        size_t off = ((size_t)b * DD + d) * HWD + p;
        float v = ksa_b[d] + g_mpart[0][off] + g_mpart[1][off]
                           + g_mpart[2][off] + g_mpart[3][off];
        g_maxout[off] = v;
        mx = fmaxf(mx, v);
        sm += v;
    }
    smx[dg][pl] = mx;
    ssm[dg][pl] = sm;
    __syncthreads();

    if (dg == 0) {
        float m = smx[0][pl], s = ssm[0][pl];
#pragma unroll
        for (int g = 1; g < 8; g++) {
            m = fmaxf(m, smx[g][pl]);
            s += ssm[g][pl];
        }
        g_qmax [gp] = m;
        g_qmean[gp] = s * (1.f / 32.f);
    }
}

// ---------------------------------------------------------------------------
// Kernel 2a: lit partials (scrambled flat view).
// ---------------------------------------------------------------------------
__global__ void k_lit_a(void)
{
    int chunk = blockIdx.x & 3;
    int bd = blockIdx.x >> 2;
    int d = bd & 31, b = bd >> 5;
    int tid = threadIdx.x;
    const float* mo = g_maxout + (size_t)b * DD * HWD;
    const float* q  = g_qmax + b * HWD;

    float part = 0.f;
#pragma unroll
    for (int k = 0; k < 4; k++) {
        int p = chunk * 1024 + tid + (k << 8);
        part += q[p] * mo[((p >> 7) << 12) + ((p & 127) << 5) + d];
    }
#pragma unroll
    for (int off = 16; off; off >>= 1)
        part += __shfl_xor_sync(0xffffffffu, part, off);

    __shared__ float sred[8];
    if ((tid & 31) == 0) sred[tid >> 5] = part;
    __syncthreads();
    if (tid == 0) {
        float s = 0.f;
#pragma unroll
        for (int w = 0; w < 8; w++) s += sred[w];
        g_litpart[blockIdx.x] = s;
    }
}

// ---------------------------------------------------------------------------
// Kernel 2b: re_score = sum_d lit[d]*mo[d][p]; scale = 1 + sigmoid.
// ---------------------------------------------------------------------------
__global__ void k_lit_b(float* __restrict__ rescore_out)
{
    __shared__ float slit[32];
    int b = blockIdx.y;
    int p = blockIdx.x * 128 + threadIdx.x;
    if (threadIdx.x < 32) {
        const float* lp = g_litpart + (b * DD + threadIdx.x) * 4;
        slit[threadIdx.x] = (lp[0] + lp[1] + lp[2] + lp[3]) * (1.f / 4096.f);
    }
    __syncthreads();

    const float* mo = g_maxout + (size_t)b * DD * HWD;
    float r = 0.f;
#pragma unroll
    for (int d = 0; d < 32; d++) r += slit[d] * mo[d * HWD + p];
    rescore_out[b * HWD + p] = r;
    g_scale[b * HWD + p] = 1.f + 1.f / (1.f + __expf(-r));
}

// ---------------------------------------------------------------------------
// Kernel W: convert K_w to fp16.
// ---------------------------------------------------------------------------
__global__ void k_wconv(const float* __restrict__ W)
{
    int i = blockIdx.x * 256 + threadIdx.x;
    g_Wh[i] = __float2half_rn(W[i]);
}

// ---------------------------------------------------------------------------
// Kernel X: convert shallow to fp16 (native [b][c][p] layout).
// ---------------------------------------------------------------------------
__global__ void k_xsplit(const float* __restrict__ X)
{
    size_t i = ((size_t)blockIdx.x * 256 + threadIdx.x) * 8;
    float4 a = *reinterpret_cast<const float4*>(X + i);
    float4 b = *reinterpret_cast<const float4*>(X + i + 4);
    __half2 h0 = __floats2half2_rn(a.x, a.y);
    __half2 h1 = __floats2half2_rn(a.z, a.w);
    __half2 h2 = __floats2half2_rn(b.x, b.y);
    __half2 h3 = __floats2half2_rn(b.z, b.w);
    uint4 hv = make_uint4(*reinterpret_cast<uint32_t*>(&h0),
                          *reinterpret_cast<uint32_t*>(&h1),
                          *reinterpret_cast<uint32_t*>(&h2),
                          *reinterpret_cast<uint32_t*>(&h3));
    *reinterpret_cast<uint4*>(g_Xh + i) = hv;
}

// ---------------------------------------------------------------------------
// Kernel 3: single fp16 GEMM via mma.sync: C = A * B + bias.
// Block 128x128, BK=32, 8 warps, 3-stage cp.async pipeline.
// A tile [m][k] pitch-80B; B tile [k][n] 256B rows, seg-XOR swizzle,
// consumed by ldmatrix.x4.trans from X's native [c][p] layout.
// ---------------------------------------------------------------------------
#define GBK  32
#define ATB  (128 * 80)               // 10240 A tile
#define BTB  (32 * 256)               // 8192  B tile
#define BUFB (ATB + BTB)              // 18432
#define NSTAGE 3
#define GSMEM (NSTAGE * BUFB)         // 55296

__global__ void __launch_bounds__(256)
k_gemm_mma(const float* __restrict__ bias)
{
    extern __shared__ char smem[];
    const uint32_t sbase = smem_u32(smem);
    const int tid  = threadIdx.x;
    const int lane = tid & 31, wid = tid >> 5;
    const int wm = wid & 1;
    const int wn = wid >> 1;
    const int n0 = blockIdx.x * 128, m0 = blockIdx.y * 128, b = blockIdx.z;

    const __half* Aw = g_Wh + (size_t)m0 * CIN;
    const __half* Bx = g_Xh + (size_t)b * CIN * PIX + n0;

    float acc[4][4][4];
#pragma unroll
    for (int i = 0; i < 4; i++)
#pragma unroll
        for (int j = 0; j < 4; j++)
#pragma unroll
            for (int k = 0; k < 4; k++) acc[i][j][k] = 0.f;

    auto issue = [&](int cidx, int buf) {
        int kc = cidx * GBK;
        uint32_t dbase = sbase + buf * BUFB;
#pragma unroll
        for (int t = 0; t < 2; t++) {
            int s = tid + t * 256;
            {   // A tile: 128 rows x 4 segs of 16B (512 slots)
                int row = s >> 2, seg = s & 3;
                uint32_t doff = row * 80 + seg * 16;
                size_t   soff = (size_t)row * CIN + kc + seg * 8;
                cp16(dbase + doff, Aw + soff);
            }
            {   // B tile: 32 k-rows x 16 segs of 16B, seg-XOR swizzle (512 slots)
                int row = s >> 4, seg = s & 15;
                uint32_t doff = row * 256 + ((seg ^ (row & 7)) << 4);
                size_t   soff = (size_t)(kc + row) * PIX + seg * 8;
                cp16(dbase + ATB + doff, Bx + soff);
            }
        }
        asm volatile("cp.async.commit_group;" ::: "memory");
    };

    auto compute = [&](int buf) {
        uint32_t base = sbase + buf * BUFB;
        int l16 = lane & 15;
        int kh8 = (lane >> 4) * 8;
        int krow_base = (lane & 7) + ((lane & 16) >> 1);
        int ncol_base = wn * 32 + (lane & 8);
#pragma unroll
        for (int ks = 0; ks < 2; ks++) {
            int kb = ks * 16 + kh8;
            uint32_t afr[4][4];
#pragma unroll
            for (int i = 0; i < 4; i++) {
                uint32_t off = (uint32_t)((wm * 64 + i * 16 + l16) * 80 + kb * 2);
                ldsm4(afr[i], base + off);
            }
            uint32_t bfr[4][2];
            {
                int krow = ks * 16 + krow_base;
                uint32_t brow = base + ATB + krow * 256;
                uint32_t sw = (uint32_t)((krow & 7) << 4);
#pragma unroll
                for (int jj = 0; jj < 2; jj++) {
                    uint32_t boff = ((uint32_t)((ncol_base + jj * 16) * 2)) ^ sw;
                    uint32_t t0[4];
                    ldsm4t(t0, brow + boff);
                    bfr[jj * 2][0]     = t0[0]; bfr[jj * 2 + 1][0] = t0[1];
                    bfr[jj * 2][1]     = t0[2]; bfr[jj * 2 + 1][1] = t0[3];
                }
            }
#pragma unroll
            for (int i = 0; i < 4; i++)
#pragma unroll
                for (int j = 0; j < 4; j++)
                    mma_f16(acc[i][j], afr[i], bfr[j]);
        }
    };

    issue(0, 0);
    issue(1, 1);
#pragma unroll 1
    for (int c = 0; c < CIN / GBK; c++) {
        asm volatile("cp.async.wait_group 1;" ::: "memory");
        __syncthreads();
        if (c + 2 < CIN / GBK) issue(c + 2, (c + 2) % NSTAGE);
        compute(c % NSTAGE);
    }

    // ---- epilogue: bias + store fp32 ----
    int r = lane >> 2, cpair = (lane & 3) * 2;
    float* Cb = g_Kx + (size_t)b * OC * PIX;
#pragma unroll
    for (int i = 0; i < 4; i++) {
        int m_g = m0 + wm * 64 + i * 16 + r;
        float b0 = bias[m_g], b1 = bias[m_g + 8];
#pragma unroll
        for (int j = 0; j < 4; j++) {
            int n_g = n0 + wn * 32 + j * 8 + cpair;
            float2 v0 = make_float2(acc[i][j][0] + b0, acc[i][j][1] + b0);
            float2 v1 = make_float2(acc[i][j][2] + b1, acc[i][j][3] + b1);
            *reinterpret_cast<float2*>(Cb + (size_t)m_g * PIX + n_g)       = v0;
            *reinterpret_cast<float2*>(Cb + (size_t)(m_g + 8) * PIX + n_g) = v1;
        }
    }
}

// ---------------------------------------------------------------------------
// Kernel 4: fused unfold(3x3, s2, p1) + softmax attention + gating.
// ---------------------------------------------------------------------------
__global__ void k_att(float* __restrict__ out)
{
    int idx = blockIdx.x * 256 + threadIdx.x;
    int p = idx & (HWD - 1);
    int o = (idx >> 12) & (OC - 1);
    int b = idx >> 20;
    int y = p >> 6, x = p & 63;

    const float* base = g_Kx + ((size_t)(b * OC + o) << 14);
    float m  = g_qmean[(b << 12) + p];
    float sc = g_scale[(b << 12) + p];

    float v[9];
    int yy0 = 2 * y - 1, xx0 = 2 * x - 1;
#pragma unroll
    for (int i = 0; i < 3; i++) {
        int yy = yy0 + i;
#pragma unroll
        for (int j = 0; j < 3; j++) {
            int xx = xx0 + j;
            v[i * 3 + j] = (yy >= 0 && xx >= 0) ? base[(yy << 7) + xx] : 0.f;
        }
    }

    float L = m * v[0];
#pragma unroll
    for (int k = 1; k < 9; k++) L = fmaxf(L, m * v[k]);
    float s = 0.f, num = 0.f;
#pragma unroll
    for (int k = 0; k < 9; k++) {
        float e = __expf(m * v[k] - L);
        s   += e;
        num += e * v[k];
    }
    out[idx] = sc * __fdividef(num, s);
}

// ---------------------------------------------------------------------------
extern "C" void kernel_launch(void* const* d_in, const int* in_sizes, int n_in,
                              void* d_out, int out_size)
{
    const float* shallow = (const float*)d_in[0];
    const float* deep    = (const float*)d_in[1];
    const float* K_w     = (const float*)d_in[2];
    const float* K_b     = (const float*)d_in[3];
    const float* KSA_w   = (const float*)d_in[4];
    const float* KSA_b   = (const float*)d_in[5];
    float* out = (float*)d_out;

    float* rescore_out = out + (size_t)BB * OC * HWD;

    cudaFuncSetAttribute(k_gemm_mma, cudaFuncAttributeMaxDynamicSharedMemorySize,
                         GSMEM);

    // k_gemm_mma stays 4th so ncu (-s 5 -c 1) captures it.
    k_wconv<<<(OC * CIN) / 256, 256>>>(K_w);
    k_xsplit<<<(int)(((size_t)BB * CIN * PIX) / (256 * 8)), 256>>>(shallow);
    k_maxout_part<<<dim3(HWD / 256, BB, 4), 128>>>(deep, KSA_w);
    k_gemm_mma<<<dim3(PIX / 128, OC / 128, BB), 256, GSMEM>>>(K_b);
    k_maxcomb<<<(BB * HWD) / 64, 512>>>(KSA_b);
    k_lit_a<<<BB * DD * 4, 256>>>();
    k_lit_b<<<dim3(HWD / 128, BB), 128>>>(rescore_out);
    k_att<<<(BB * OC * HWD) / 256, 256>>>(out);
}